// round 8
// baseline (speedup 1.0000x reference)
#include <cuda_runtime.h>

#define N_ELEMS 33554432
#define N8 (N_ELEMS / 8)   // 4194304 8-float work items
#define THREADS 256

__device__ __forceinline__ void ldg256(const float* p, float r[8]) {
    asm("ld.global.nc.v8.f32 {%0,%1,%2,%3,%4,%5,%6,%7}, [%8];"
        : "=f"(r[0]), "=f"(r[1]), "=f"(r[2]), "=f"(r[3]),
          "=f"(r[4]), "=f"(r[5]), "=f"(r[6]), "=f"(r[7])
        : "l"(p));
}

__device__ __forceinline__ void stg256(float* p, const float r[8]) {
    asm volatile("st.global.v8.f32 [%0], {%1,%2,%3,%4,%5,%6,%7,%8};"
        :: "l"(p),
           "f"(r[0]), "f"(r[1]), "f"(r[2]), "f"(r[3]),
           "f"(r[4]), "f"(r[5]), "f"(r[6]), "f"(r[7])
        : "memory");
}

__global__ __launch_bounds__(THREADS) void ssvi_kernel(
    const float* __restrict__ logm,
    const float* __restrict__ yATM,
    const float* __restrict__ raw_rho,
    const float* __restrict__ raw_eta,
    const float* __restrict__ raw_gamma,
    float* __restrict__ out)
{
    const size_t base = ((size_t)blockIdx.x * THREADS + threadIdx.x) * 8;

    float lm[8], y[8];
    ldg256(logm + base, lm);
    ldg256(yATM + base, y);

    // Broadcast scalars (tiny, cached)
    const float rho   = tanhf(__ldg(&raw_rho[0]));
    const float eta   = __expf(__ldg(&raw_eta[0]));
    const float gamma = __expf(__ldg(&raw_gamma[0]));
    const float one_m_rho2 = 1.0f - rho * rho;

    float o[8], g1[8], g2[8];

    #pragma unroll
    for (int c = 0; c < 8; ++c) {
        float lmv = lm[c];
        float yv  = y[c];

        // phi = eta / (y^gamma * (1+y)^(1-gamma))
        float ly  = __logf(yv);
        float l1y = __logf(1.0f + yv);
        float phi = eta * __expf(-(gamma * ly + (1.0f - gamma) * l1y));

        float pl  = phi * lmv;
        float arg = fmaf(pl, pl, fmaf(2.0f * rho, pl, 1.0f));  // pl^2 + 2 rho pl + 1
        float invS = rsqrtf(arg);
        float S    = arg * invS;
        float half_y = 0.5f * yv;

        o[c]  = half_y * (1.0f + rho * pl + S);
        g1[c] = half_y * phi * (rho + (pl + rho) * invS);
        float invS3 = invS * invS * invS;
        g2[c] = half_y * phi * phi * one_m_rho2 * invS3;
    }

    stg256(out + base,                        o);   // output
    stg256(out + 2 * (size_t)N_ELEMS + base,  g1);  // grad_logm1
    stg256(out + 3 * (size_t)N_ELEMS + base,  g2);  // grad_logm2
    // grad_ttm1 zeros handled by cudaMemsetAsync in kernel_launch
}

extern "C" void kernel_launch(void* const* d_in, const int* in_sizes, int n_in,
                              void* d_out, int out_size)
{
    const float* logm = (const float*)d_in[0];
    const float* yATM = (const float*)d_in[1];
    const float* raw_rho   = (const float*)d_in[2];
    const float* raw_eta   = (const float*)d_in[3];
    const float* raw_gamma = (const float*)d_in[4];
    float* out = (float*)d_out;

    // Zero the grad_ttm1 quarter via the dedicated memset path (pure-write,
    // near-peak BW; graph-capturable; not an allocation).
    cudaMemsetAsync(out + (size_t)N_ELEMS, 0, (size_t)N_ELEMS * sizeof(float));

    const int blocks = N8 / THREADS;  // exact: 4194304 / 256 = 16384
    ssvi_kernel<<<blocks, THREADS>>>(logm, yATM, raw_rho, raw_eta, raw_gamma, out);
}

// round 9
// speedup vs baseline: 1.0131x; 1.0131x over previous
#include <cuda_runtime.h>

#define N_ELEMS 33554432
#define N8 (N_ELEMS / 8)   // 4194304 8-float work items
#define THREADS 256

__device__ __forceinline__ void ldg256(const float* p, float r[8]) {
    asm("ld.global.nc.v8.f32 {%0,%1,%2,%3,%4,%5,%6,%7}, [%8];"
        : "=f"(r[0]), "=f"(r[1]), "=f"(r[2]), "=f"(r[3]),
          "=f"(r[4]), "=f"(r[5]), "=f"(r[6]), "=f"(r[7])
        : "l"(p));
}

__device__ __forceinline__ void stg256(float* p, const float r[8]) {
    asm volatile("st.global.v8.f32 [%0], {%1,%2,%3,%4,%5,%6,%7,%8};"
        :: "l"(p),
           "f"(r[0]), "f"(r[1]), "f"(r[2]), "f"(r[3]),
           "f"(r[4]), "f"(r[5]), "f"(r[6]), "f"(r[7])
        : "memory");
}

// Pure-write zero fill: most favorable DRAM pattern (no reads, no turnaround).
__global__ __launch_bounds__(THREADS) void zero_kernel(float* __restrict__ dst)
{
    const size_t base = ((size_t)blockIdx.x * THREADS + threadIdx.x) * 8;
    const float z[8] = {0.f, 0.f, 0.f, 0.f, 0.f, 0.f, 0.f, 0.f};
    stg256(dst + base, z);
}

__global__ __launch_bounds__(THREADS) void ssvi_kernel(
    const float* __restrict__ logm,
    const float* __restrict__ yATM,
    const float* __restrict__ raw_rho,
    const float* __restrict__ raw_eta,
    const float* __restrict__ raw_gamma,
    float* __restrict__ out)
{
    const size_t base = ((size_t)blockIdx.x * THREADS + threadIdx.x) * 8;

    float lm[8], y[8];
    ldg256(logm + base, lm);
    ldg256(yATM + base, y);

    // Broadcast scalars (tiny, cached)
    const float rho   = tanhf(__ldg(&raw_rho[0]));
    const float eta   = __expf(__ldg(&raw_eta[0]));
    const float gamma = __expf(__ldg(&raw_gamma[0]));
    const float one_m_rho2 = 1.0f - rho * rho;

    float o[8], g1[8], g2[8];

    #pragma unroll
    for (int c = 0; c < 8; ++c) {
        float lmv = lm[c];
        float yv  = y[c];

        // phi = eta / (y^gamma * (1+y)^(1-gamma))
        float ly  = __logf(yv);
        float l1y = __logf(1.0f + yv);
        float phi = eta * __expf(-(gamma * ly + (1.0f - gamma) * l1y));

        float pl  = phi * lmv;
        float arg = fmaf(pl, pl, fmaf(2.0f * rho, pl, 1.0f));  // pl^2 + 2 rho pl + 1
        float invS = rsqrtf(arg);
        float S    = arg * invS;
        float half_y = 0.5f * yv;

        o[c]  = half_y * (1.0f + rho * pl + S);
        g1[c] = half_y * phi * (rho + (pl + rho) * invS);
        float invS3 = invS * invS * invS;
        g2[c] = half_y * phi * phi * one_m_rho2 * invS3;
    }

    stg256(out + base,                        o);   // output
    stg256(out + 2 * (size_t)N_ELEMS + base,  g1);  // grad_logm1
    stg256(out + 3 * (size_t)N_ELEMS + base,  g2);  // grad_logm2
    // grad_ttm1 zeros handled by zero_kernel
}

extern "C" void kernel_launch(void* const* d_in, const int* in_sizes, int n_in,
                              void* d_out, int out_size)
{
    const float* logm = (const float*)d_in[0];
    const float* yATM = (const float*)d_in[1];
    const float* raw_rho   = (const float*)d_in[2];
    const float* raw_eta   = (const float*)d_in[3];
    const float* raw_gamma = (const float*)d_in[4];
    float* out = (float*)d_out;

    const int blocks = N8 / THREADS;  // exact: 4194304 / 256 = 16384
    ssvi_kernel<<<blocks, THREADS>>>(logm, yATM, raw_rho, raw_eta, raw_gamma, out);
    zero_kernel<<<blocks, THREADS>>>(out + (size_t)N_ELEMS);  // grad_ttm1 quarter
}